// round 5
// baseline (speedup 1.0000x reference)
#include <cuda_runtime.h>

typedef unsigned long long u64;
#define BATCH 131072

// inter-phase state: concat layout [b][96], enc at 0..63, cent at 64..95
__device__ float g_h0[(size_t)BATCH * 96];
__device__ float g_c0[(size_t)BATCH * 96];

__device__ __forceinline__ float ex2f(float x){ float y; asm("ex2.approx.f32 %0, %1;" : "=f"(y) : "f"(x)); return y; }
__device__ __forceinline__ float rcpf(float x){ float y; asm("rcp.approx.f32 %0, %1;" : "=f"(y) : "f"(x)); return y; }
__device__ __forceinline__ float sigmf(float x){ return rcpf(1.0f + ex2f(-1.4426950408889634f * x)); }
__device__ __forceinline__ float tanhf_(float x){ return 1.0f - 2.0f * rcpf(1.0f + ex2f(2.8853900817779268f * x)); }

// packed dual-fp32 FMA: d.lo += a.lo*b.lo ; d.hi += a.hi*b.hi
__device__ __forceinline__ void ffma2(u64 &d, u64 a, u64 b){
    asm("fma.rn.f32x2 %0, %1, %2, %0;" : "+l"(d) : "l"(a), "l"(b));
}
__device__ __forceinline__ u64 dup2(float w){
    u64 r; asm("mov.b64 %0, {%1, %1};" : "=l"(r) : "f"(w)); return r;
}
__device__ __forceinline__ float2 u2f(u64 a){
    float2 r; asm("mov.b64 {%0, %1}, %2;" : "=f"(r.x), "=f"(r.y) : "l"(a)); return r;
}
__device__ __forceinline__ u64 f2u(float2 v){
    u64 r; asm("mov.b64 %0, {%1, %2};" : "=l"(r) : "f"(v.x), "f"(v.y)); return r;
}

// ---------------------------------------------------------------------------
// cent / enc recurrent phase. NT = H*ETC threads. Thread (rt=unit, et=8-elem
// tile) computes 4 gate rows x 8 elems, element-packed f32x2 accumulators.
// W pre-duplicated as (w,w) u64 pairs in SMEM -> LDS.64 broadcast, no movs.
// h stored [k][e] (e contiguous), double-buffered x in SMEM.
// ---------------------------------------------------------------------------
template<int H, int T, int ETC, int OFF>
__global__ __launch_bounds__(H * ETC)
void lstm_rec(const float* __restrict__ x_g,
              const float* __restrict__ Wih, const float* __restrict__ Whh,
              const float* __restrict__ bih, const float* __restrict__ bhh)
{
    constexpr int NT = H * ETC;
    constexpr int G  = 4 * H;
    constexpr int NE = ETC * 8;
    constexpr int HP = NE + 4;
    extern __shared__ float sm[];
    float* hsm = sm;                 // [H][HP]
    float* Wd  = hsm + H * HP;       // [G][H] as u64 pairs -> 2*G*H floats
    float* bsd = Wd + 2 * G * H;     // [G] u64 pairs
    float* xs0 = bsd + 2 * G;        // [2][NE] x-dim0, double buffered
    float* xs1 = xs0 + 2 * NE;       // [2][NE] x-dim1

    const int tid = threadIdx.x;
    for (int i = tid; i < G * H; i += NT){
        float w = Whh[i];
        Wd[2 * i] = w; Wd[2 * i + 1] = w;
    }
    for (int i = tid; i < G; i += NT){
        float bv = bih[i] + bhh[i];
        bsd[2 * i] = bv; bsd[2 * i + 1] = bv;
    }
    for (int i = tid; i < H * HP; i += NT) hsm[i] = 0.0f;

    const int et = tid % ETC, rt = tid / ETC;
    const int e0 = et * 8;
    const size_t b0 = (size_t)blockIdx.x * NE;

    // per-thread x-projection weights [gate][x-dim]
    float wxr[4][2];
    #pragma unroll
    for (int gt = 0; gt < 4; gt++){
        wxr[gt][0] = Wih[(gt * H + rt) * 2];
        wxr[gt][1] = Wih[(gt * H + rt) * 2 + 1];
    }

    u64 cc[4];
    #pragma unroll
    for (int ep = 0; ep < 4; ep++) cc[ep] = 0ULL;

    if (tid < NE){
        float2 v = *(const float2*)(x_g + (b0 + tid) * (size_t)(2 * T));
        xs0[tid] = v.x; xs1[tid] = v.y;
    }
    __syncthreads();

    const u64* Wp = (const u64*)Wd;
    int wrow[4];
    #pragma unroll
    for (int gt = 0; gt < 4; gt++) wrow[gt] = (gt * H + rt) * H;

    for (int t = 0; t < T; t++){
        const int cur = t & 1, nxt = cur ^ 1;
        float2 xn = make_float2(0.f, 0.f);
        if (t + 1 < T && tid < NE)
            xn = *(const float2*)(x_g + (b0 + tid) * (size_t)(2 * T) + 2 * (t + 1));

        u64 acc[4][4];
        #pragma unroll
        for (int gt = 0; gt < 4; gt++){
            u64 bv = *(const u64*)&bsd[2 * (gt * H + rt)];
            #pragma unroll
            for (int ep = 0; ep < 4; ep++) acc[gt][ep] = bv;
        }

        const float* hk = hsm + e0;
        #pragma unroll 4
        for (int k = 0; k < H; k++){
            ulonglong2 ha = *(const ulonglong2*)(hk);
            ulonglong2 hb = *(const ulonglong2*)(hk + 4);
            #pragma unroll
            for (int gt = 0; gt < 4; gt++){
                u64 wd = Wp[wrow[gt] + k];
                ffma2(acc[gt][0], wd, ha.x);
                ffma2(acc[gt][1], wd, ha.y);
                ffma2(acc[gt][2], wd, hb.x);
                ffma2(acc[gt][3], wd, hb.y);
            }
            hk += HP;
        }

        float x0v[8], x1v[8];
        #pragma unroll
        for (int i = 0; i < 8; i++){ x0v[i] = xs0[cur * NE + e0 + i]; x1v[i] = xs1[cur * NE + e0 + i]; }

        float hnv[8];
        #pragma unroll
        for (int ep = 0; ep < 4; ep++){
            float2 gi = u2f(acc[0][ep]);
            float2 gf = u2f(acc[1][ep]);
            float2 gg = u2f(acc[2][ep]);
            float2 go = u2f(acc[3][ep]);
            float2 cv = u2f(cc[ep]);
            #pragma unroll
            for (int m = 0; m < 2; m++){
                const int e = 2 * ep + m;
                float giX = (m ? gi.y : gi.x) + x0v[e] * wxr[0][0] + x1v[e] * wxr[0][1];
                float gfX = (m ? gf.y : gf.x) + x0v[e] * wxr[1][0] + x1v[e] * wxr[1][1];
                float ggX = (m ? gg.y : gg.x) + x0v[e] * wxr[2][0] + x1v[e] * wxr[2][1];
                float goX = (m ? go.y : go.x) + x0v[e] * wxr[3][0] + x1v[e] * wxr[3][1];
                float cn = sigmf(gfX) * (m ? cv.y : cv.x) + sigmf(giX) * tanhf_(ggX);
                if (m) cv.y = cn; else cv.x = cn;
                hnv[e] = sigmf(goX) * tanhf_(cn);
            }
            cc[ep] = f2u(cv);
        }

        __syncthreads();
        if (t + 1 < T && tid < NE){ xs0[nxt * NE + tid] = xn.x; xs1[nxt * NE + tid] = xn.y; }
        {
            float* hw = hsm + rt * HP + e0;
            *(float4*)hw       = make_float4(hnv[0], hnv[1], hnv[2], hnv[3]);
            *(float4*)(hw + 4) = make_float4(hnv[4], hnv[5], hnv[6], hnv[7]);
        }
        __syncthreads();
    }

    // coalesced h writeback: hsm[j][e] -> g_h0[(b0+e)*96 + OFF + j]
    for (int i = tid; i < NE * H; i += NT){
        int e = i / H, j = i % H;
        g_h0[(b0 + e) * 96 + OFF + j] = hsm[j * HP + e];
    }
    __syncthreads();
    // stage c into hsm, then coalesced writeback
    #pragma unroll
    for (int ep = 0; ep < 4; ep++){
        float2 cv = u2f(cc[ep]);
        hsm[rt * HP + e0 + 2 * ep]     = cv.x;
        hsm[rt * HP + e0 + 2 * ep + 1] = cv.y;
    }
    __syncthreads();
    for (int i = tid; i < NE * H; i += NT){
        int e = i / H, j = i % H;
        g_c0[(b0 + e) * 96 + OFF + j] = hsm[j * HP + e];
    }
}

// ---------------------------------------------------------------------------
// decoder: H=96, 30 steps, x == h -> W = Wih+Whh, bias = bih+bhh.
// NT=768 (96 units x 8 e-tiles), NE=64. Scalar W + dup mov (dup'd W = 294KB
// won't fit). pos via packed (x,y) dot, 64 threads.
// ---------------------------------------------------------------------------
#define DNT 768
__global__ __launch_bounds__(DNT)
void lstm_dec(const float* __restrict__ Wih, const float* __restrict__ Whh,
              const float* __restrict__ bih, const float* __restrict__ bhh,
              const float* __restrict__ Wemb, const float* __restrict__ bemb,
              float* __restrict__ out)
{
    constexpr int H = 96, G = 384, ETC = 8, NE = ETC * 8, WP = H + 1, HP = NE + 4;
    extern __shared__ float sm[];
    float* hsm = sm;                 // [H][HP]
    float* W   = hsm + H * HP;       // [G][WP]
    float* bsd = W + G * WP;         // [G] u64 pairs
    float* we2 = bsd + 2 * G;        // [H][2] (wex, wey)
    float* csm = we2 + 2 * H;        // [H][HP]

    const int tid = threadIdx.x;
    for (int i = tid; i < G * H; i += DNT) W[(i / H) * WP + (i % H)] = Wih[i] + Whh[i];
    for (int i = tid; i < G; i += DNT){ float bv = bih[i] + bhh[i]; bsd[2*i] = bv; bsd[2*i+1] = bv; }
    for (int i = tid; i < H; i += DNT){ we2[2*i] = Wemb[i]; we2[2*i+1] = Wemb[96 + i]; }

    const int et = tid % ETC, rt = tid / ETC;
    const int e0 = et * 8;
    const size_t b0 = (size_t)blockIdx.x * NE;

    // coalesced load of h,c; transpose into SMEM [j][e]
    for (int i4 = tid; i4 < NE * H / 4; i4 += DNT){
        int e = (4 * i4) / H, j = (4 * i4) % H;
        float4 hv = *(const float4*)(g_h0 + (b0 + e) * 96 + j);
        float4 cv = *(const float4*)(g_c0 + (b0 + e) * 96 + j);
        hsm[(j+0) * HP + e] = hv.x; hsm[(j+1) * HP + e] = hv.y;
        hsm[(j+2) * HP + e] = hv.z; hsm[(j+3) * HP + e] = hv.w;
        csm[(j+0) * HP + e] = cv.x; csm[(j+1) * HP + e] = cv.y;
        csm[(j+2) * HP + e] = cv.z; csm[(j+3) * HP + e] = cv.w;
    }
    __syncthreads();

    u64 cc[4];
    #pragma unroll
    for (int ep = 0; ep < 4; ep++){
        float2 cv;
        cv.x = csm[rt * HP + e0 + 2 * ep];
        cv.y = csm[rt * HP + e0 + 2 * ep + 1];
        cc[ep] = f2u(cv);
    }
    const float bex = bemb[0], bey = bemb[1];

    int wrow[4];
    #pragma unroll
    for (int gt = 0; gt < 4; gt++) wrow[gt] = (gt * H + rt) * WP;

    for (int t = 0; t < 30; t++){
        u64 acc[4][4];
        #pragma unroll
        for (int gt = 0; gt < 4; gt++){
            u64 bv = *(const u64*)&bsd[2 * (gt * H + rt)];
            #pragma unroll
            for (int ep = 0; ep < 4; ep++) acc[gt][ep] = bv;
        }

        const float* hk = hsm + e0;
        #pragma unroll 4
        for (int k = 0; k < H; k++){
            ulonglong2 ha = *(const ulonglong2*)(hk);
            ulonglong2 hb = *(const ulonglong2*)(hk + 4);
            #pragma unroll
            for (int gt = 0; gt < 4; gt++){
                u64 wd = dup2(W[wrow[gt] + k]);
                ffma2(acc[gt][0], wd, ha.x);
                ffma2(acc[gt][1], wd, ha.y);
                ffma2(acc[gt][2], wd, hb.x);
                ffma2(acc[gt][3], wd, hb.y);
            }
            hk += HP;
        }

        float hnv[8];
        #pragma unroll
        for (int ep = 0; ep < 4; ep++){
            float2 gi = u2f(acc[0][ep]);
            float2 gf = u2f(acc[1][ep]);
            float2 gg = u2f(acc[2][ep]);
            float2 go = u2f(acc[3][ep]);
            float2 cv = u2f(cc[ep]);
            #pragma unroll
            for (int m = 0; m < 2; m++){
                float cn = sigmf(m ? gf.y : gf.x) * (m ? cv.y : cv.x)
                         + sigmf(m ? gi.y : gi.x) * tanhf_(m ? gg.y : gg.x);
                if (m) cv.y = cn; else cv.x = cn;
                hnv[2 * ep + m] = sigmf(m ? go.y : go.x) * tanhf_(cn);
            }
            cc[ep] = f2u(cv);
        }

        __syncthreads();
        {
            float* hw = hsm + rt * HP + e0;
            *(float4*)hw       = make_float4(hnv[0], hnv[1], hnv[2], hnv[3]);
            *(float4*)(hw + 4) = make_float4(hnv[4], hnv[5], hnv[6], hnv[7]);
        }
        __syncthreads();

        // pos output: 64 threads, one element each, packed (x,y) dot
        if (tid < NE){
            u64 ap = 0ULL;
            const float* hp = hsm + tid;
            #pragma unroll 8
            for (int j = 0; j < H; j++){
                u64 hd = dup2(hp[j * HP]);
                ffma2(ap, hd, *(const u64*)&we2[2 * j]);
            }
            float2 p = u2f(ap);
            float2 o; o.x = p.x + bex; o.y = p.y + bey;
            *(float2*)(out + (b0 + tid) * 60 + 2 * t) = o;
        }
    }
}

extern "C" void kernel_launch(void* const* d_in, const int* in_sizes, int n_in,
                              void* d_out, int out_size)
{
    (void)n_in; (void)out_size;
    const float* traj  = (const float*)d_in[0];
    const float* cent  = (const float*)d_in[1];
    const float* Wih_c = (const float*)d_in[2];
    const float* Whh_c = (const float*)d_in[3];
    const float* bih_c = (const float*)d_in[4];
    const float* bhh_c = (const float*)d_in[5];
    const float* Wih_e = (const float*)d_in[6];
    const float* Whh_e = (const float*)d_in[7];
    const float* bih_e = (const float*)d_in[8];
    const float* bhh_e = (const float*)d_in[9];
    const float* Wih_d = (const float*)d_in[10];
    const float* Whh_d = (const float*)d_in[11];
    const float* bih_d = (const float*)d_in[12];
    const float* bhh_d = (const float*)d_in[13];
    const float* W_emb = (const float*)d_in[14];
    const float* b_emb = (const float*)d_in[15];
    float* out = (float*)d_out;

    const int B = in_sizes[0] / 40;   // input_traj [B][20][2]

    // SMEM bytes
    const int smc = (32*132 + 2*128*32 + 2*128 + 4*128) * 4;   //  52,736  (NE=128)
    const int sme = (64*68 + 2*256*64 + 2*256 + 4*64) * 4;     // 151,552  (NE=64)
    const int smd = (96*68 + 384*97 + 2*384 + 2*96 + 96*68)*4; // 205,056  (NE=64)

    cudaFuncSetAttribute(lstm_rec<32,100,16,64>, cudaFuncAttributeMaxDynamicSharedMemorySize, smc);
    cudaFuncSetAttribute(lstm_rec<64, 20, 8, 0>, cudaFuncAttributeMaxDynamicSharedMemorySize, sme);
    cudaFuncSetAttribute(lstm_dec, cudaFuncAttributeMaxDynamicSharedMemorySize, smd);

    // centerline LSTM (H=32, T=100, NT=512, NE=128) -> g_h0/g_c0[.., 64..95]
    lstm_rec<32,100,16,64><<<B/128, 512, smc>>>(cent, Wih_c, Whh_c, bih_c, bhh_c);
    // encoder LSTM (H=64, T=20, NT=512, NE=64)      -> g_h0/g_c0[.., 0..63]
    lstm_rec<64, 20, 8, 0><<<B/64, 512, sme>>>(traj, Wih_e, Whh_e, bih_e, bhh_e);
    // decoder (H=96, 30 steps, NT=768, NE=64) -> out [B][30][2]
    lstm_dec<<<B/64, DNT, smd>>>(Wih_d, Whh_d, bih_d, bhh_d, W_emb, b_emb, out);
}

// round 6
// speedup vs baseline: 1.6439x; 1.6439x over previous
#include <cuda_runtime.h>

typedef unsigned long long u64;
#define BATCH 131072

// inter-phase state: concat layout [b][96], enc at 0..63, cent at 64..95
__device__ float g_h0[(size_t)BATCH * 96];
__device__ float g_c0[(size_t)BATCH * 96];

__device__ __forceinline__ float ex2f(float x){ float y; asm("ex2.approx.f32 %0, %1;" : "=f"(y) : "f"(x)); return y; }
__device__ __forceinline__ float rcpf(float x){ float y; asm("rcp.approx.f32 %0, %1;" : "=f"(y) : "f"(x)); return y; }
__device__ __forceinline__ float sigmf(float x){ return rcpf(1.0f + ex2f(-1.4426950408889634f * x)); }
__device__ __forceinline__ float tanhf_(float x){ return 1.0f - 2.0f * rcpf(1.0f + ex2f(2.8853900817779268f * x)); }

// packed dual-fp32 FMA: d.lo += a.lo*b.lo ; d.hi += a.hi*b.hi
__device__ __forceinline__ void ffma2(u64 &d, u64 a, u64 b){
    asm("fma.rn.f32x2 %0, %1, %2, %0;" : "+l"(d) : "l"(a), "l"(b));
}
__device__ __forceinline__ float red2(u64 a){
    float lo, hi; asm("mov.b64 {%0, %1}, %2;" : "=f"(lo), "=f"(hi) : "l"(a)); return lo + hi;
}

// ---------------------------------------------------------------------------
// cent / enc phase, k-pair packed. NT = 4*H. Thread (rt = unit-pair, et):
// 8 gate rows {2rt,2rt+1}x4 gates x 4 elems (e = sub*8 + et), acc u64 holds
// k-even/k-odd partials. W k-major [G][H+2] (LDS.64 pairs, no dup);
// h transposed [e][H+6] (LDS.64 pairs). 12 LDS + 32 ffma2 per k-pair.
// ---------------------------------------------------------------------------
template<int H, int T, int OFF, int MINB>
__global__ __launch_bounds__(4 * H, MINB)
void lstm_rec(const float* __restrict__ x_g,
              const float* __restrict__ Wih, const float* __restrict__ Whh,
              const float* __restrict__ bih, const float* __restrict__ bhh)
{
    constexpr int NT = 4 * H;
    constexpr int G  = 4 * H;
    constexpr int NE = 32;
    constexpr int WP = H + 2;
    constexpr int HP = H + 6;
    extern __shared__ float sm[];
    float* W   = sm;               // [G][WP] k-major
    float* wxs = W + G * WP;       // [G][2]
    float* hsm = wxs + 2 * G;      // [NE][HP] transposed h

    const int tid = threadIdx.x;
    for (int i = tid; i < G * H; i += NT) W[(i / H) * WP + (i % H)] = Whh[i];
    for (int i = tid; i < 2 * G; i += NT) wxs[i] = Wih[i];
    for (int i = tid; i < NE * HP; i += NT) hsm[i] = 0.0f;

    const int et = tid & 7, rt = tid >> 3;
    const int j0 = 2 * rt;
    const size_t b0 = (size_t)blockIdx.x * NE;

    float bb[4][2];
    #pragma unroll
    for (int gt = 0; gt < 4; gt++)
        #pragma unroll
        for (int uu = 0; uu < 2; uu++){
            int r = gt * H + j0 + uu;
            bb[gt][uu] = bih[r] + bhh[r];
        }

    float c2[2][4];
    #pragma unroll
    for (int uu = 0; uu < 2; uu++)
        #pragma unroll
        for (int sub = 0; sub < 4; sub++) c2[uu][sub] = 0.0f;

    __syncthreads();

    for (int t = 0; t < T; t++){
        // x for this thread's 4 elems (consumed only in epilogue -> LDG hidden by k-loop)
        float2 xv[4];
        #pragma unroll
        for (int sub = 0; sub < 4; sub++)
            xv[sub] = *(const float2*)(x_g + (b0 + sub * 8 + et) * (size_t)(2 * T) + 2 * t);

        u64 acc[4][2][4];
        #pragma unroll
        for (int gt = 0; gt < 4; gt++)
            #pragma unroll
            for (int uu = 0; uu < 2; uu++)
                #pragma unroll
                for (int sub = 0; sub < 4; sub++) acc[gt][uu][sub] = 0ULL;

        #pragma unroll 8
        for (int kk = 0; kk < H / 2; kk++){
            u64 hv[4];
            #pragma unroll
            for (int sub = 0; sub < 4; sub++)
                hv[sub] = *(const u64*)&hsm[(sub * 8 + et) * HP + 2 * kk];
            #pragma unroll
            for (int gt = 0; gt < 4; gt++)
                #pragma unroll
                for (int uu = 0; uu < 2; uu++){
                    u64 wv = *(const u64*)&W[(gt * H + j0 + uu) * WP + 2 * kk];
                    ffma2(acc[gt][uu][0], wv, hv[0]);
                    ffma2(acc[gt][uu][1], wv, hv[1]);
                    ffma2(acc[gt][uu][2], wv, hv[2]);
                    ffma2(acc[gt][uu][3], wv, hv[3]);
                }
        }

        // x-projection weights (broadcast loads, once per step)
        float wxl[4][2][2];
        #pragma unroll
        for (int gt = 0; gt < 4; gt++)
            #pragma unroll
            for (int uu = 0; uu < 2; uu++){
                wxl[gt][uu][0] = wxs[(gt * H + j0 + uu) * 2];
                wxl[gt][uu][1] = wxs[(gt * H + j0 + uu) * 2 + 1];
            }

        float hnew[2][4];
        #pragma unroll
        for (int uu = 0; uu < 2; uu++)
            #pragma unroll
            for (int sub = 0; sub < 4; sub++){
                float x0 = xv[sub].x, x1 = xv[sub].y;
                float gi = red2(acc[0][uu][sub]) + bb[0][uu] + x0 * wxl[0][uu][0] + x1 * wxl[0][uu][1];
                float gf = red2(acc[1][uu][sub]) + bb[1][uu] + x0 * wxl[1][uu][0] + x1 * wxl[1][uu][1];
                float gg = red2(acc[2][uu][sub]) + bb[2][uu] + x0 * wxl[2][uu][0] + x1 * wxl[2][uu][1];
                float go = red2(acc[3][uu][sub]) + bb[3][uu] + x0 * wxl[3][uu][0] + x1 * wxl[3][uu][1];
                float cn = sigmf(gf) * c2[uu][sub] + sigmf(gi) * tanhf_(gg);
                c2[uu][sub] = cn;
                hnew[uu][sub] = sigmf(go) * tanhf_(cn);
            }

        __syncthreads();   // all h reads done
        #pragma unroll
        for (int sub = 0; sub < 4; sub++)
            *(float2*)&hsm[(sub * 8 + et) * HP + j0] = make_float2(hnew[0][sub], hnew[1][sub]);
        __syncthreads();   // h update visible
    }

    // h writeback (coalesced per elem row)
    for (int i = tid; i < NE * H; i += NT){
        int e = i / H, j = i % H;
        g_h0[(b0 + e) * 96 + OFF + j] = hsm[e * HP + j];
    }
    // c writeback (pairwise STG.64)
    #pragma unroll
    for (int sub = 0; sub < 4; sub++)
        *(float2*)&g_c0[(b0 + sub * 8 + et) * 96 + OFF + j0] = make_float2(c2[0][sub], c2[1][sub]);
}

// ---------------------------------------------------------------------------
// decoder: H=96, 30 steps, x == h -> W = Wih+Whh, bias = bih+bhh.
// Same k-pair packing. NT=384, NE=32, 1 CTA/SM (W=150KB). pos by warp 0.
// ---------------------------------------------------------------------------
#define DNT 384
__global__ __launch_bounds__(DNT, 1)
void lstm_dec(const float* __restrict__ Wih, const float* __restrict__ Whh,
              const float* __restrict__ bih, const float* __restrict__ bhh,
              const float* __restrict__ Wemb, const float* __restrict__ bemb,
              float* __restrict__ out)
{
    constexpr int H = 96, G = 384, NE = 32, WP = H + 2, HP = H + 6;
    extern __shared__ float sm[];
    float* W   = sm;               // [G][WP] merged Wih+Whh, k-major
    float* wex = W + G * WP;       // [96]
    float* wey = wex + 96;         // [96]
    float* hsm = wey + 96;         // [NE][HP]

    const int tid = threadIdx.x;
    for (int i = tid; i < G * H; i += DNT) W[(i / H) * WP + (i % H)] = Wih[i] + Whh[i];
    for (int i = tid; i < 96; i += DNT){ wex[i] = Wemb[i]; wey[i] = Wemb[96 + i]; }

    const int et = tid & 7, rt = tid >> 3;
    const int j0 = 2 * rt;
    const size_t b0 = (size_t)blockIdx.x * NE;

    float bb[4][2];
    #pragma unroll
    for (int gt = 0; gt < 4; gt++)
        #pragma unroll
        for (int uu = 0; uu < 2; uu++){
            int r = gt * H + j0 + uu;
            bb[gt][uu] = bih[r] + bhh[r];
        }
    const float be0 = bemb[0], be1 = bemb[1];

    // init h (transposed, coalesced) and c (pairwise)
    for (int i = tid; i < NE * H; i += DNT){
        int e = i / H, j = i % H;
        hsm[e * HP + j] = g_h0[(b0 + e) * 96 + j];
    }
    float c2[2][4];
    #pragma unroll
    for (int sub = 0; sub < 4; sub++){
        float2 v = *(const float2*)&g_c0[(b0 + sub * 8 + et) * 96 + j0];
        c2[0][sub] = v.x; c2[1][sub] = v.y;
    }
    __syncthreads();

    for (int t = 0; t < 30; t++){
        u64 acc[4][2][4];
        #pragma unroll
        for (int gt = 0; gt < 4; gt++)
            #pragma unroll
            for (int uu = 0; uu < 2; uu++)
                #pragma unroll
                for (int sub = 0; sub < 4; sub++) acc[gt][uu][sub] = 0ULL;

        #pragma unroll 8
        for (int kk = 0; kk < H / 2; kk++){
            u64 hv[4];
            #pragma unroll
            for (int sub = 0; sub < 4; sub++)
                hv[sub] = *(const u64*)&hsm[(sub * 8 + et) * HP + 2 * kk];
            #pragma unroll
            for (int gt = 0; gt < 4; gt++)
                #pragma unroll
                for (int uu = 0; uu < 2; uu++){
                    u64 wv = *(const u64*)&W[(gt * H + j0 + uu) * WP + 2 * kk];
                    ffma2(acc[gt][uu][0], wv, hv[0]);
                    ffma2(acc[gt][uu][1], wv, hv[1]);
                    ffma2(acc[gt][uu][2], wv, hv[2]);
                    ffma2(acc[gt][uu][3], wv, hv[3]);
                }
        }

        float hnew[2][4];
        #pragma unroll
        for (int uu = 0; uu < 2; uu++)
            #pragma unroll
            for (int sub = 0; sub < 4; sub++){
                float gi = red2(acc[0][uu][sub]) + bb[0][uu];
                float gf = red2(acc[1][uu][sub]) + bb[1][uu];
                float gg = red2(acc[2][uu][sub]) + bb[2][uu];
                float go = red2(acc[3][uu][sub]) + bb[3][uu];
                float cn = sigmf(gf) * c2[uu][sub] + sigmf(gi) * tanhf_(gg);
                c2[uu][sub] = cn;
                hnew[uu][sub] = sigmf(go) * tanhf_(cn);
            }

        __syncthreads();
        #pragma unroll
        for (int sub = 0; sub < 4; sub++)
            *(float2*)&hsm[(sub * 8 + et) * HP + j0] = make_float2(hnew[0][sub], hnew[1][sub]);
        __syncthreads();

        // pos output: warp 0, one elem per lane, k-pair packed dots
        if (tid < NE){
            u64 ax = 0ULL, ay = 0ULL;
            const float* hp = hsm + tid * HP;
            #pragma unroll 8
            for (int kk = 0; kk < H / 2; kk++){
                u64 hd = *(const u64*)&hp[2 * kk];
                ffma2(ax, hd, *(const u64*)&wex[2 * kk]);
                ffma2(ay, hd, *(const u64*)&wey[2 * kk]);
            }
            float2 o; o.x = red2(ax) + be0; o.y = red2(ay) + be1;
            *(float2*)(out + (b0 + tid) * 60 + 2 * t) = o;
        }
    }
}

extern "C" void kernel_launch(void* const* d_in, const int* in_sizes, int n_in,
                              void* d_out, int out_size)
{
    (void)n_in; (void)out_size;
    const float* traj  = (const float*)d_in[0];
    const float* cent  = (const float*)d_in[1];
    const float* Wih_c = (const float*)d_in[2];
    const float* Whh_c = (const float*)d_in[3];
    const float* bih_c = (const float*)d_in[4];
    const float* bhh_c = (const float*)d_in[5];
    const float* Wih_e = (const float*)d_in[6];
    const float* Whh_e = (const float*)d_in[7];
    const float* bih_e = (const float*)d_in[8];
    const float* bhh_e = (const float*)d_in[9];
    const float* Wih_d = (const float*)d_in[10];
    const float* Whh_d = (const float*)d_in[11];
    const float* bih_d = (const float*)d_in[12];
    const float* bhh_d = (const float*)d_in[13];
    const float* W_emb = (const float*)d_in[14];
    const float* b_emb = (const float*)d_in[15];
    float* out = (float*)d_out;

    const int B = in_sizes[0] / 40;   // input_traj [B][20][2]

    // SMEM bytes: W[4H][H+2] + wx[4H][2] + h[32][H+6]
    const int smc = (128 * 34 + 256 + 32 * 38) * 4;            //  23,296
    const int sme = (256 * 66 + 512 + 32 * 70) * 4;            //  78,592
    const int smd = (384 * 98 + 96 + 96 + 32 * 102) * 4;       // 164,352

    cudaFuncSetAttribute(lstm_rec<32, 100, 64, 4>, cudaFuncAttributeMaxDynamicSharedMemorySize, smc);
    cudaFuncSetAttribute(lstm_rec<64,  20,  0, 2>, cudaFuncAttributeMaxDynamicSharedMemorySize, sme);
    cudaFuncSetAttribute(lstm_dec, cudaFuncAttributeMaxDynamicSharedMemorySize, smd);

    // centerline LSTM (H=32, T=100) -> g_h0/g_c0[.., 64..95]
    lstm_rec<32, 100, 64, 4><<<B / 32, 128, smc>>>(cent, Wih_c, Whh_c, bih_c, bhh_c);
    // encoder LSTM (H=64, T=20)    -> g_h0/g_c0[.., 0..63]
    lstm_rec<64,  20,  0, 2><<<B / 32, 256, sme>>>(traj, Wih_e, Whh_e, bih_e, bhh_e);
    // decoder (H=96, 30 steps) -> out [B][30][2]
    lstm_dec<<<B / 32, DNT, smd>>>(Wih_d, Whh_d, bih_d, bhh_d, W_emb, b_emb, out);
}

// round 8
// speedup vs baseline: 2.0657x; 1.2566x over previous
#include <cuda_runtime.h>
#include <cuda_bf16.h>

typedef unsigned long long u64;
typedef unsigned int u32;
#define BATCH 131072

// inter-phase state: concat layout [b][96], enc at 0..63, cent at 64..95
__device__ float g_h0[(size_t)BATCH * 96];
__device__ float g_c0[(size_t)BATCH * 96];

__device__ __forceinline__ float ex2f(float x){ float y; asm("ex2.approx.f32 %0, %1;" : "=f"(y) : "f"(x)); return y; }
__device__ __forceinline__ float rcpf(float x){ float y; asm("rcp.approx.f32 %0, %1;" : "=f"(y) : "f"(x)); return y; }
__device__ __forceinline__ float sigmf(float x){ return rcpf(1.0f + ex2f(-1.4426950408889634f * x)); }
__device__ __forceinline__ float tanhf_(float x){ return 1.0f - 2.0f * rcpf(1.0f + ex2f(2.8853900817779268f * x)); }

__device__ __forceinline__ void ffma2(u64 &d, u64 a, u64 b){
    asm("fma.rn.f32x2 %0, %1, %2, %0;" : "+l"(d) : "l"(a), "l"(b));
}
__device__ __forceinline__ float red2(u64 a){
    float lo, hi; asm("mov.b64 {%0, %1}, %2;" : "=f"(lo), "=f"(hi) : "l"(a)); return lo + hi;
}
__device__ __forceinline__ u32 smem_u32(const void* p){
    u32 a; asm("{ .reg .u64 t; cvta.to.shared.u64 t, %1; cvt.u32.u64 %0, t; }" : "=r"(a) : "l"(p)); return a;
}

// ---------------------------------------------------------------------------
// cent / enc phase (unchanged from round 6 — passing, fma-bound scalar path)
// ---------------------------------------------------------------------------
template<int H, int T, int OFF, int MINB>
__global__ __launch_bounds__(4 * H, MINB)
void lstm_rec(const float* __restrict__ x_g,
              const float* __restrict__ Wih, const float* __restrict__ Whh,
              const float* __restrict__ bih, const float* __restrict__ bhh)
{
    constexpr int NT = 4 * H;
    constexpr int G  = 4 * H;
    constexpr int NE = 32;
    constexpr int WP = H + 2;
    constexpr int HP = H + 6;
    extern __shared__ float sm[];
    float* W   = sm;               // [G][WP] k-major
    float* wxs = W + G * WP;       // [G][2]
    float* hsm = wxs + 2 * G;      // [NE][HP] transposed h

    const int tid = threadIdx.x;
    for (int i = tid; i < G * H; i += NT) W[(i / H) * WP + (i % H)] = Whh[i];
    for (int i = tid; i < 2 * G; i += NT) wxs[i] = Wih[i];
    for (int i = tid; i < NE * HP; i += NT) hsm[i] = 0.0f;

    const int et = tid & 7, rt = tid >> 3;
    const int j0 = 2 * rt;
    const size_t b0 = (size_t)blockIdx.x * NE;

    float bb[4][2];
    #pragma unroll
    for (int gt = 0; gt < 4; gt++)
        #pragma unroll
        for (int uu = 0; uu < 2; uu++){
            int r = gt * H + j0 + uu;
            bb[gt][uu] = bih[r] + bhh[r];
        }

    float c2[2][4];
    #pragma unroll
    for (int uu = 0; uu < 2; uu++)
        #pragma unroll
        for (int sub = 0; sub < 4; sub++) c2[uu][sub] = 0.0f;

    __syncthreads();

    for (int t = 0; t < T; t++){
        float2 xv[4];
        #pragma unroll
        for (int sub = 0; sub < 4; sub++)
            xv[sub] = *(const float2*)(x_g + (b0 + sub * 8 + et) * (size_t)(2 * T) + 2 * t);

        u64 acc[4][2][4];
        #pragma unroll
        for (int gt = 0; gt < 4; gt++)
            #pragma unroll
            for (int uu = 0; uu < 2; uu++)
                #pragma unroll
                for (int sub = 0; sub < 4; sub++) acc[gt][uu][sub] = 0ULL;

        #pragma unroll 8
        for (int kk = 0; kk < H / 2; kk++){
            u64 hv[4];
            #pragma unroll
            for (int sub = 0; sub < 4; sub++)
                hv[sub] = *(const u64*)&hsm[(sub * 8 + et) * HP + 2 * kk];
            #pragma unroll
            for (int gt = 0; gt < 4; gt++)
                #pragma unroll
                for (int uu = 0; uu < 2; uu++){
                    u64 wv = *(const u64*)&W[(gt * H + j0 + uu) * WP + 2 * kk];
                    ffma2(acc[gt][uu][0], wv, hv[0]);
                    ffma2(acc[gt][uu][1], wv, hv[1]);
                    ffma2(acc[gt][uu][2], wv, hv[2]);
                    ffma2(acc[gt][uu][3], wv, hv[3]);
                }
        }

        float wxl[4][2][2];
        #pragma unroll
        for (int gt = 0; gt < 4; gt++)
            #pragma unroll
            for (int uu = 0; uu < 2; uu++){
                wxl[gt][uu][0] = wxs[(gt * H + j0 + uu) * 2];
                wxl[gt][uu][1] = wxs[(gt * H + j0 + uu) * 2 + 1];
            }

        float hnew[2][4];
        #pragma unroll
        for (int uu = 0; uu < 2; uu++)
            #pragma unroll
            for (int sub = 0; sub < 4; sub++){
                float x0 = xv[sub].x, x1 = xv[sub].y;
                float gi = red2(acc[0][uu][sub]) + bb[0][uu] + x0 * wxl[0][uu][0] + x1 * wxl[0][uu][1];
                float gf = red2(acc[1][uu][sub]) + bb[1][uu] + x0 * wxl[1][uu][0] + x1 * wxl[1][uu][1];
                float gg = red2(acc[2][uu][sub]) + bb[2][uu] + x0 * wxl[2][uu][0] + x1 * wxl[2][uu][1];
                float go = red2(acc[3][uu][sub]) + bb[3][uu] + x0 * wxl[3][uu][0] + x1 * wxl[3][uu][1];
                float cn = sigmf(gf) * c2[uu][sub] + sigmf(gi) * tanhf_(gg);
                c2[uu][sub] = cn;
                hnew[uu][sub] = sigmf(go) * tanhf_(cn);
            }

        __syncthreads();
        #pragma unroll
        for (int sub = 0; sub < 4; sub++)
            *(float2*)&hsm[(sub * 8 + et) * HP + j0] = make_float2(hnew[0][sub], hnew[1][sub]);
        __syncthreads();
    }

    for (int i = tid; i < NE * H; i += NT){
        int e = i / H, j = i % H;
        g_h0[(b0 + e) * 96 + OFF + j] = hsm[e * HP + j];
    }
    #pragma unroll
    for (int sub = 0; sub < 4; sub++)
        *(float2*)&g_c0[(b0 + sub * 8 + et) * 96 + OFF + j0] = make_float2(c2[0][sub], c2[1][sub]);
}

// ---------------------------------------------------------------------------
// decoder on warp-level HMMA (mma.sync m16n8k16 bf16, split hi/lo).
// NE=32 elems/CTA, 512 thr = 16 warps: rg = wid>>3 (2 row groups x 16 elems),
// cg = wid&7 (8 col groups x 48 gate-cols). W gate-interleaved: col r = 4j+g.
// ---------------------------------------------------------------------------
#define DNT 512
// SMEM byte offsets
#define SW_HI   0          // W_hi  [384][104] bf16  (79,872)
#define SW_LO   79872      // W_lo  [384][104] bf16  (79,872)
#define SH_HI   159744     // h_hi  [32][104]  bf16  (6,656)
#define SH_LO   166400     // h_lo  [32][104]  bf16  (6,656)
#define SH_F32  173056     // h_f32 [32][100]  f32   (12,800)
#define S_BSD   185856     // bias  [384]      f32   (1,536)
#define S_WEX   187392     // [96] f32
#define S_WEY   187776     // [96] f32
#define SM_TOT  188160
#define WROW    208        // bytes per 104-bf16 row
#define HF32P   100

__device__ __forceinline__ void ldsm4(u32 &r0, u32 &r1, u32 &r2, u32 &r3, u32 addr){
    asm volatile("ldmatrix.sync.aligned.m8n8.x4.shared.b16 {%0,%1,%2,%3}, [%4];"
        : "=r"(r0), "=r"(r1), "=r"(r2), "=r"(r3) : "r"(addr));
}
__device__ __forceinline__ void ldsm2(u32 &r0, u32 &r1, u32 addr){
    asm volatile("ldmatrix.sync.aligned.m8n8.x2.shared.b16 {%0,%1}, [%2];"
        : "=r"(r0), "=r"(r1) : "r"(addr));
}
__device__ __forceinline__ void mma_bf16(float &d0, float &d1, float &d2, float &d3,
                                         const u32* a, u32 b0, u32 b1){
    asm volatile("mma.sync.aligned.m16n8k16.row.col.f32.bf16.bf16.f32 "
        "{%0,%1,%2,%3}, {%4,%5,%6,%7}, {%8,%9}, {%0,%1,%2,%3};"
        : "+f"(d0), "+f"(d1), "+f"(d2), "+f"(d3)
        : "r"(a[0]), "r"(a[1]), "r"(a[2]), "r"(a[3]), "r"(b0), "r"(b1));
}

__global__ __launch_bounds__(DNT, 1)
void lstm_dec_mma(const float* __restrict__ Wih, const float* __restrict__ Whh,
                  const float* __restrict__ bih, const float* __restrict__ bhh,
                  const float* __restrict__ Wemb, const float* __restrict__ bemb,
                  float* __restrict__ out)
{
    extern __shared__ char smc[];
    float* hf32 = (float*)(smc + SH_F32);
    float* bsd  = (float*)(smc + S_BSD);
    float* wex  = (float*)(smc + S_WEX);
    float* wey  = (float*)(smc + S_WEY);
    const u32 smb = smem_u32(smc);

    const int tid = threadIdx.x;
    const size_t b0 = (size_t)blockIdx.x * 32;

    // ---- W fill: torch row = g*96+j -> interleaved col r = 4j+g, bf16 split ----
    for (int i = tid; i < 384 * 96; i += DNT){
        int trow = i / 96, k = i % 96;
        int g = trow / 96 % 4, j = trow % 96;
        float w = Wih[i] + Whh[i];
        __nv_bfloat16 hi = __float2bfloat16(w);
        __nv_bfloat16 lo = __float2bfloat16(w - __bfloat162float(hi));
        int r = 4 * j + g;
        *(__nv_bfloat16*)(smc + SW_HI + (r * 104 + k) * 2) = hi;
        *(__nv_bfloat16*)(smc + SW_LO + (r * 104 + k) * 2) = lo;
    }
    for (int i = tid; i < 384; i += DNT){
        int g = i / 96, j = i % 96;
        bsd[4 * j + g] = bih[i] + bhh[i];
    }
    for (int i = tid; i < 96; i += DNT){ wex[i] = Wemb[i]; wey[i] = Wemb[96 + i]; }

    // ---- h0 into SMEM (f32 + bf16 split) ----
    for (int i = tid; i < 32 * 96; i += DNT){
        int e = i / 96, j = i % 96;
        float v = g_h0[(b0 + e) * 96 + j];
        __nv_bfloat16 hi = __float2bfloat16(v);
        __nv_bfloat16 lo = __float2bfloat16(v - __bfloat162float(hi));
        hf32[e * HF32P + j] = v;
        *(__nv_bfloat16*)(smc + SH_HI + (e * 104 + j) * 2) = hi;
        *(__nv_bfloat16*)(smc + SH_LO + (e * 104 + j) * 2) = lo;
    }

    const int wid = tid >> 5, lane = tid & 31;
    const int cg = wid & 7, rg = wid >> 3;
    const int e0 = rg * 16, colbase = cg * 48;
    const int tg = lane & 3, gq = lane >> 2;
    const bool is_even = (tg & 1) == 0;

    // ldmatrix per-lane addresses
    const int a_row = e0 + (lane & 7) + ((lane >> 3) & 1) * 8;
    const u32 a_koff = ((lane >> 4) & 1) * 16;
    const u32 ah_base = smb + SH_HI + (u32)a_row * WROW + a_koff;
    const u32 al_base = smb + SH_LO + (u32)a_row * WROW + a_koff;
    const int b_lane = lane & 15;
    const int b_row = colbase + (b_lane & 7);
    const u32 b_koff = ((b_lane >> 3) & 1) * 16;
    const u32 bh_base = smb + SW_HI + (u32)b_row * WROW + b_koff;
    const u32 bl_base = smb + SW_LO + (u32)b_row * WROW + b_koff;

    // c state (meaningful on even-tg lanes): cell = (tile n0, rows e0+gq / +8)
    float cA[6], cB[6];
    #pragma unroll
    for (int n0 = 0; n0 < 6; n0++){
        int j = cg * 12 + n0 * 2 + (tg >> 1);
        cA[n0] = g_c0[(b0 + e0 + gq) * 96 + j];
        cB[n0] = g_c0[(b0 + e0 + gq + 8) * 96 + j];
    }
    const float bex = bemb[0], bey = bemb[1];
    __syncthreads();

    for (int t = 0; t < 30; t++){
        // load A fragments (h hi/lo), 6 k-chunks
        u32 ahi[6][4], alo[6][4];
        #pragma unroll
        for (int kc = 0; kc < 6; kc++){
            ldsm4(ahi[kc][0], ahi[kc][1], ahi[kc][2], ahi[kc][3], ah_base + kc * 32);
            ldsm4(alo[kc][0], alo[kc][1], alo[kc][2], alo[kc][3], al_base + kc * 32);
        }
        __syncthreads();   // A consumed -> h SMEM writable

        #pragma unroll
        for (int n0 = 0; n0 < 6; n0++){
            float d0 = 0.f, d1 = 0.f, d2 = 0.f, d3 = 0.f;
            const u32 bo_n = (u32)(n0 * 8) * WROW;
            #pragma unroll
            for (int kc = 0; kc < 6; kc++){
                u32 bh0, bh1, bl0, bl1;
                ldsm2(bh0, bh1, bh_base + bo_n + kc * 32);
                ldsm2(bl0, bl1, bl_base + bo_n + kc * 32);
                mma_bf16(d0, d1, d2, d3, ahi[kc], bh0, bh1);
                mma_bf16(d0, d1, d2, d3, alo[kc], bh0, bh1);
                mma_bf16(d0, d1, d2, d3, ahi[kc], bl0, bl1);
            }
            // pair exchange: even lanes hold (i,f), receive (g,o) from lane^1
            float s0 = __shfl_xor_sync(0xffffffffu, d0, 1);
            float s1 = __shfl_xor_sync(0xffffffffu, d1, 1);
            float s2 = __shfl_xor_sync(0xffffffffu, d2, 1);
            float s3 = __shfl_xor_sync(0xffffffffu, d3, 1);
            if (is_even){
                const int r = colbase + n0 * 8 + 2 * tg;   // = 4j
                const int j = r >> 2;
                float bi = bsd[r], bf = bsd[r + 1], bg = bsd[r + 2], bo = bsd[r + 3];
                const int eA = e0 + gq, eB = eA + 8;
                float cnA = sigmf(d1 + bf) * cA[n0] + sigmf(d0 + bi) * tanhf_(s0 + bg);
                float hA  = sigmf(s1 + bo) * tanhf_(cnA);
                float cnB = sigmf(d3 + bf) * cB[n0] + sigmf(d2 + bi) * tanhf_(s2 + bg);
                float hB  = sigmf(s3 + bo) * tanhf_(cnB);
                cA[n0] = cnA; cB[n0] = cnB;
                hf32[eA * HF32P + j] = hA;
                hf32[eB * HF32P + j] = hB;
                __nv_bfloat16 hAh = __float2bfloat16(hA);
                __nv_bfloat16 hBh = __float2bfloat16(hB);
                *(__nv_bfloat16*)(smc + SH_HI + (eA * 104 + j) * 2) = hAh;
                *(__nv_bfloat16*)(smc + SH_HI + (eB * 104 + j) * 2) = hBh;
                *(__nv_bfloat16*)(smc + SH_LO + (eA * 104 + j) * 2) = __float2bfloat16(hA - __bfloat162float(hAh));
                *(__nv_bfloat16*)(smc + SH_LO + (eB * 104 + j) * 2) = __float2bfloat16(hB - __bfloat162float(hBh));
            }
        }
        __syncthreads();   // h ready

        // pos output: warp 0, lane = elem, k-pair packed ffma2 dot
        if (tid < 32){
            u64 ax = 0ULL, ay = 0ULL;
            const float* hp = hf32 + tid * HF32P;
            #pragma unroll 8
            for (int kk = 0; kk < 48; kk++){
                u64 hd = *(const u64*)&hp[2 * kk];
                ffma2(ax, hd, *(const u64*)&wex[2 * kk]);
                ffma2(ay, hd, *(const u64*)&wey[2 * kk]);
            }
            float2 o; o.x = red2(ax) + bex; o.y = red2(ay) + bey;
            *(float2*)(out + (b0 + tid) * 60 + 2 * t) = o;
        }
    }
}

extern "C" void kernel_launch(void* const* d_in, const int* in_sizes, int n_in,
                              void* d_out, int out_size)
{
    (void)n_in; (void)out_size;
    const float* traj  = (const float*)d_in[0];
    const float* cent  = (const float*)d_in[1];
    const float* Wih_c = (const float*)d_in[2];
    const float* Whh_c = (const float*)d_in[3];
    const float* bih_c = (const float*)d_in[4];
    const float* bhh_c = (const float*)d_in[5];
    const float* Wih_e = (const float*)d_in[6];
    const float* Whh_e = (const float*)d_in[7];
    const float* bih_e = (const float*)d_in[8];
    const float* bhh_e = (const float*)d_in[9];
    const float* Wih_d = (const float*)d_in[10];
    const float* Whh_d = (const float*)d_in[11];
    const float* bih_d = (const float*)d_in[12];
    const float* bhh_d = (const float*)d_in[13];
    const float* W_emb = (const float*)d_in[14];
    const float* b_emb = (const float*)d_in[15];
    float* out = (float*)d_out;

    const int B = in_sizes[0] / 40;   // input_traj [B][20][2]

    const int smc = (128 * 34 + 256 + 32 * 38) * 4;            //  23,296
    const int sme = (256 * 66 + 512 + 32 * 70) * 4;            //  78,592

    cudaFuncSetAttribute(lstm_rec<32, 100, 64, 4>, cudaFuncAttributeMaxDynamicSharedMemorySize, smc);
    cudaFuncSetAttribute(lstm_rec<64,  20,  0, 2>, cudaFuncAttributeMaxDynamicSharedMemorySize, sme);
    cudaFuncSetAttribute(lstm_dec_mma, cudaFuncAttributeMaxDynamicSharedMemorySize, SM_TOT);

    // centerline LSTM (H=32, T=100) -> g_h0/g_c0[.., 64..95]
    lstm_rec<32, 100, 64, 4><<<B / 32, 128, smc>>>(cent, Wih_c, Whh_c, bih_c, bhh_c);
    // encoder LSTM (H=64, T=20)    -> g_h0/g_c0[.., 0..63]
    lstm_rec<64,  20,  0, 2><<<B / 32, 256, sme>>>(traj, Wih_e, Whh_e, bih_e, bhh_e);
    // decoder on HMMA (H=96, 30 steps, 32 elems/CTA) -> out [B][30][2]
    lstm_dec_mma<<<B / 32, DNT, SM_TOT>>>(Wih_d, Whh_d, bih_d, bhh_d, W_emb, b_emb, out);
}

// round 9
// speedup vs baseline: 2.2041x; 1.0670x over previous
#include <cuda_runtime.h>
#include <cuda_fp16.h>

typedef unsigned long long u64;
typedef unsigned int u32;
#define BATCH 131072

// inter-phase state: concat layout [b][96], enc at 0..63, cent at 64..95
__device__ float g_h0[(size_t)BATCH * 96];
__device__ float g_c0[(size_t)BATCH * 96];

__device__ __forceinline__ float ex2f(float x){ float y; asm("ex2.approx.f32 %0, %1;" : "=f"(y) : "f"(x)); return y; }
__device__ __forceinline__ float rcpf(float x){ float y; asm("rcp.approx.f32 %0, %1;" : "=f"(y) : "f"(x)); return y; }
__device__ __forceinline__ float sigmf(float x){ return rcpf(1.0f + ex2f(-1.4426950408889634f * x)); }
__device__ __forceinline__ float tanhf_(float x){ return 1.0f - 2.0f * rcpf(1.0f + ex2f(2.8853900817779268f * x)); }

__device__ __forceinline__ void ffma2(u64 &d, u64 a, u64 b){
    asm("fma.rn.f32x2 %0, %1, %2, %0;" : "+l"(d) : "l"(a), "l"(b));
}
__device__ __forceinline__ float red2(u64 a){
    float lo, hi; asm("mov.b64 {%0, %1}, %2;" : "=f"(lo), "=f"(hi) : "l"(a)); return lo + hi;
}
__device__ __forceinline__ u32 smem_u32(const void* p){
    u32 a; asm("{ .reg .u64 t; cvta.to.shared.u64 t, %1; cvt.u32.u64 %0, t; }" : "=r"(a) : "l"(p)); return a;
}

// ---------------------------------------------------------------------------
// cent / enc phase (unchanged — passing, fma-bound scalar path)
// ---------------------------------------------------------------------------
template<int H, int T, int OFF, int MINB>
__global__ __launch_bounds__(4 * H, MINB)
void lstm_rec(const float* __restrict__ x_g,
              const float* __restrict__ Wih, const float* __restrict__ Whh,
              const float* __restrict__ bih, const float* __restrict__ bhh)
{
    constexpr int NT = 4 * H;
    constexpr int G  = 4 * H;
    constexpr int NE = 32;
    constexpr int WP = H + 2;
    constexpr int HP = H + 6;
    extern __shared__ float sm[];
    float* W   = sm;               // [G][WP] k-major
    float* wxs = W + G * WP;       // [G][2]
    float* hsm = wxs + 2 * G;      // [NE][HP] transposed h

    const int tid = threadIdx.x;
    for (int i = tid; i < G * H; i += NT) W[(i / H) * WP + (i % H)] = Whh[i];
    for (int i = tid; i < 2 * G; i += NT) wxs[i] = Wih[i];
    for (int i = tid; i < NE * HP; i += NT) hsm[i] = 0.0f;

    const int et = tid & 7, rt = tid >> 3;
    const int j0 = 2 * rt;
    const size_t b0 = (size_t)blockIdx.x * NE;

    float bb[4][2];
    #pragma unroll
    for (int gt = 0; gt < 4; gt++)
        #pragma unroll
        for (int uu = 0; uu < 2; uu++){
            int r = gt * H + j0 + uu;
            bb[gt][uu] = bih[r] + bhh[r];
        }

    float c2[2][4];
    #pragma unroll
    for (int uu = 0; uu < 2; uu++)
        #pragma unroll
        for (int sub = 0; sub < 4; sub++) c2[uu][sub] = 0.0f;

    __syncthreads();

    for (int t = 0; t < T; t++){
        float2 xv[4];
        #pragma unroll
        for (int sub = 0; sub < 4; sub++)
            xv[sub] = *(const float2*)(x_g + (b0 + sub * 8 + et) * (size_t)(2 * T) + 2 * t);

        u64 acc[4][2][4];
        #pragma unroll
        for (int gt = 0; gt < 4; gt++)
            #pragma unroll
            for (int uu = 0; uu < 2; uu++)
                #pragma unroll
                for (int sub = 0; sub < 4; sub++) acc[gt][uu][sub] = 0ULL;

        #pragma unroll 8
        for (int kk = 0; kk < H / 2; kk++){
            u64 hv[4];
            #pragma unroll
            for (int sub = 0; sub < 4; sub++)
                hv[sub] = *(const u64*)&hsm[(sub * 8 + et) * HP + 2 * kk];
            #pragma unroll
            for (int gt = 0; gt < 4; gt++)
                #pragma unroll
                for (int uu = 0; uu < 2; uu++){
                    u64 wv = *(const u64*)&W[(gt * H + j0 + uu) * WP + 2 * kk];
                    ffma2(acc[gt][uu][0], wv, hv[0]);
                    ffma2(acc[gt][uu][1], wv, hv[1]);
                    ffma2(acc[gt][uu][2], wv, hv[2]);
                    ffma2(acc[gt][uu][3], wv, hv[3]);
                }
        }

        float wxl[4][2][2];
        #pragma unroll
        for (int gt = 0; gt < 4; gt++)
            #pragma unroll
            for (int uu = 0; uu < 2; uu++){
                wxl[gt][uu][0] = wxs[(gt * H + j0 + uu) * 2];
                wxl[gt][uu][1] = wxs[(gt * H + j0 + uu) * 2 + 1];
            }

        float hnew[2][4];
        #pragma unroll
        for (int uu = 0; uu < 2; uu++)
            #pragma unroll
            for (int sub = 0; sub < 4; sub++){
                float x0 = xv[sub].x, x1 = xv[sub].y;
                float gi = red2(acc[0][uu][sub]) + bb[0][uu] + x0 * wxl[0][uu][0] + x1 * wxl[0][uu][1];
                float gf = red2(acc[1][uu][sub]) + bb[1][uu] + x0 * wxl[1][uu][0] + x1 * wxl[1][uu][1];
                float gg = red2(acc[2][uu][sub]) + bb[2][uu] + x0 * wxl[2][uu][0] + x1 * wxl[2][uu][1];
                float go = red2(acc[3][uu][sub]) + bb[3][uu] + x0 * wxl[3][uu][0] + x1 * wxl[3][uu][1];
                float cn = sigmf(gf) * c2[uu][sub] + sigmf(gi) * tanhf_(gg);
                c2[uu][sub] = cn;
                hnew[uu][sub] = sigmf(go) * tanhf_(cn);
            }

        __syncthreads();
        #pragma unroll
        for (int sub = 0; sub < 4; sub++)
            *(float2*)&hsm[(sub * 8 + et) * HP + j0] = make_float2(hnew[0][sub], hnew[1][sub]);
        __syncthreads();
    }

    for (int i = tid; i < NE * H; i += NT){
        int e = i / H, j = i % H;
        g_h0[(b0 + e) * 96 + OFF + j] = hsm[e * HP + j];
    }
    #pragma unroll
    for (int sub = 0; sub < 4; sub++)
        *(float2*)&g_c0[(b0 + sub * 8 + et) * 96 + OFF + j0] = make_float2(c2[0][sub], c2[1][sub]);
}

// ---------------------------------------------------------------------------
// decoder on HMMA, fp16 2-pass: gates = (h_hi + h_lo) @ fp16(W)^T.
// W quantized to fp16 (static ~2^-11 rel err); h split keeps state exact.
// B fragments loaded via ldsm.x4 over n-tile pairs (3 pairs of 8-col tiles).
// ---------------------------------------------------------------------------
#define DNT 512
// SMEM byte offsets
#define SW_HI   0          // W_hi  [384][104] fp16  (79,872)
#define SH_HI   79872      // h_hi  [32][104]  fp16  (6,656)
#define SH_LO   86528      // h_lo  [32][104]  fp16  (6,656)
#define SH_F32  93184      // h_f32 [32][100]  f32   (12,800)
#define S_BSD   105984     // bias  [384]      f32   (1,536)
#define S_WEX   107520     // [96] f32
#define S_WEY   107904     // [96] f32
#define SM_TOT  108288
#define WROW    208        // bytes per 104-half row
#define HF32P   100

__device__ __forceinline__ void ldsm4(u32 &r0, u32 &r1, u32 &r2, u32 &r3, u32 addr){
    asm volatile("ldmatrix.sync.aligned.m8n8.x4.shared.b16 {%0,%1,%2,%3}, [%4];"
        : "=r"(r0), "=r"(r1), "=r"(r2), "=r"(r3) : "r"(addr));
}
__device__ __forceinline__ void mma_f16(float &d0, float &d1, float &d2, float &d3,
                                        const u32* a, u32 b0, u32 b1){
    asm volatile("mma.sync.aligned.m16n8k16.row.col.f32.f16.f16.f32 "
        "{%0,%1,%2,%3}, {%4,%5,%6,%7}, {%8,%9}, {%0,%1,%2,%3};"
        : "+f"(d0), "+f"(d1), "+f"(d2), "+f"(d3)
        : "r"(a[0]), "r"(a[1]), "r"(a[2]), "r"(a[3]), "r"(b0), "r"(b1));
}

__global__ __launch_bounds__(DNT, 1)
void lstm_dec_mma(const float* __restrict__ Wih, const float* __restrict__ Whh,
                  const float* __restrict__ bih, const float* __restrict__ bhh,
                  const float* __restrict__ Wemb, const float* __restrict__ bemb,
                  float* __restrict__ out)
{
    extern __shared__ char smc[];
    float* hf32 = (float*)(smc + SH_F32);
    float* bsd  = (float*)(smc + S_BSD);
    float* wex  = (float*)(smc + S_WEX);
    float* wey  = (float*)(smc + S_WEY);
    const u32 smb = smem_u32(smc);

    const int tid = threadIdx.x;
    const size_t b0 = (size_t)blockIdx.x * 32;

    // ---- W fill: torch row = g*96+j -> interleaved col r = 4j+g, fp16 ----
    for (int i = tid; i < 384 * 96; i += DNT){
        int trow = i / 96, k = i % 96;
        int g = trow / 96 % 4, j = trow % 96;
        float w = Wih[i] + Whh[i];
        int r = 4 * j + g;
        *(__half*)(smc + SW_HI + (r * 104 + k) * 2) = __float2half_rn(w);
    }
    for (int i = tid; i < 384; i += DNT){
        int g = i / 96, j = i % 96;
        bsd[4 * j + g] = bih[i] + bhh[i];
    }
    for (int i = tid; i < 96; i += DNT){ wex[i] = Wemb[i]; wey[i] = Wemb[96 + i]; }

    // ---- h0 into SMEM (f32 + fp16 split) ----
    for (int i = tid; i < 32 * 96; i += DNT){
        int e = i / 96, j = i % 96;
        float v = g_h0[(b0 + e) * 96 + j];
        __half hi = __float2half_rn(v);
        __half lo = __float2half_rn(v - __half2float(hi));
        hf32[e * HF32P + j] = v;
        *(__half*)(smc + SH_HI + (e * 104 + j) * 2) = hi;
        *(__half*)(smc + SH_LO + (e * 104 + j) * 2) = lo;
    }

    const int wid = tid >> 5, lane = tid & 31;
    const int cg = wid & 7, rg = wid >> 3;
    const int e0 = rg * 16, colbase = cg * 48;
    const int tg = lane & 3, gq = lane >> 2;
    const bool is_even = (tg & 1) == 0;

    // ldmatrix per-lane addresses (A: x4 over m16k16; B: x4 over n-pair k16)
    const int a_row = e0 + (lane & 7) + ((lane >> 3) & 1) * 8;
    const u32 a_koff = ((lane >> 4) & 1) * 16;
    const u32 ah_base = smb + SH_HI + (u32)a_row * WROW + a_koff;
    const u32 al_base = smb + SH_LO + (u32)a_row * WROW + a_koff;
    const int b4_row = colbase + ((lane >> 4) << 3) + (lane & 7);
    const u32 b4_koff = ((lane >> 3) & 1) * 16;
    const u32 b4_base = smb + SW_HI + (u32)b4_row * WROW + b4_koff;

    // c state (meaningful on even-tg lanes): cell = (tile n0, rows e0+gq / +8)
    float cA[6], cB[6];
    #pragma unroll
    for (int n0 = 0; n0 < 6; n0++){
        int j = cg * 12 + n0 * 2 + (tg >> 1);
        cA[n0] = g_c0[(b0 + e0 + gq) * 96 + j];
        cB[n0] = g_c0[(b0 + e0 + gq + 8) * 96 + j];
    }
    const float bex = bemb[0], bey = bemb[1];
    __syncthreads();

    for (int t = 0; t < 30; t++){
        // load A fragments (h hi/lo), 6 k-chunks
        u32 ahi[6][4], alo[6][4];
        #pragma unroll
        for (int kc = 0; kc < 6; kc++){
            ldsm4(ahi[kc][0], ahi[kc][1], ahi[kc][2], ahi[kc][3], ah_base + kc * 32);
            ldsm4(alo[kc][0], alo[kc][1], alo[kc][2], alo[kc][3], al_base + kc * 32);
        }
        __syncthreads();   // A consumed -> h SMEM writable

        #pragma unroll
        for (int p = 0; p < 3; p++){
            float d[2][4];
            #pragma unroll
            for (int h2 = 0; h2 < 2; h2++)
                #pragma unroll
                for (int r2 = 0; r2 < 4; r2++) d[h2][r2] = 0.f;
            const u32 bp = b4_base + (u32)(p * 16) * WROW;
            #pragma unroll
            for (int kc = 0; kc < 6; kc++){
                u32 bq0, bq1, bq2, bq3;
                ldsm4(bq0, bq1, bq2, bq3, bp + kc * 32);
                mma_f16(d[0][0], d[0][1], d[0][2], d[0][3], ahi[kc], bq0, bq1);
                mma_f16(d[0][0], d[0][1], d[0][2], d[0][3], alo[kc], bq0, bq1);
                mma_f16(d[1][0], d[1][1], d[1][2], d[1][3], ahi[kc], bq2, bq3);
                mma_f16(d[1][0], d[1][1], d[1][2], d[1][3], alo[kc], bq2, bq3);
            }
            #pragma unroll
            for (int h2 = 0; h2 < 2; h2++){
                const int n0 = 2 * p + h2;
                float d0 = d[h2][0], d1 = d[h2][1], d2 = d[h2][2], d3 = d[h2][3];
                // pair exchange: even lanes hold (i,f), receive (g,o) from lane^1
                float s0 = __shfl_xor_sync(0xffffffffu, d0, 1);
                float s1 = __shfl_xor_sync(0xffffffffu, d1, 1);
                float s2 = __shfl_xor_sync(0xffffffffu, d2, 1);
                float s3 = __shfl_xor_sync(0xffffffffu, d3, 1);
                if (is_even){
                    const int r = colbase + n0 * 8 + 2 * tg;   // = 4j
                    const int j = r >> 2;
                    float bi = bsd[r], bf = bsd[r + 1], bg = bsd[r + 2], bo = bsd[r + 3];
                    const int eA = e0 + gq, eB = eA + 8;
                    float cnA = sigmf(d1 + bf) * cA[n0] + sigmf(d0 + bi) * tanhf_(s0 + bg);
                    float hA  = sigmf(s1 + bo) * tanhf_(cnA);
                    float cnB = sigmf(d3 + bf) * cB[n0] + sigmf(d2 + bi) * tanhf_(s2 + bg);
                    float hB  = sigmf(s3 + bo) * tanhf_(cnB);
                    cA[n0] = cnA; cB[n0] = cnB;
                    hf32[eA * HF32P + j] = hA;
                    hf32[eB * HF32P + j] = hB;
                    __half hAh = __float2half_rn(hA);
                    __half hBh = __float2half_rn(hB);
                    *(__half*)(smc + SH_HI + (eA * 104 + j) * 2) = hAh;
                    *(__half*)(smc + SH_HI + (eB * 104 + j) * 2) = hBh;
                    *(__half*)(smc + SH_LO + (eA * 104 + j) * 2) = __float2half_rn(hA - __half2float(hAh));
                    *(__half*)(smc + SH_LO + (eB * 104 + j) * 2) = __float2half_rn(hB - __half2float(hBh));
                }
            }
        }
        __syncthreads();   // h ready

        // pos output: warp 0, lane = elem, k-pair packed ffma2 dot
        if (tid < 32){
            u64 ax = 0ULL, ay = 0ULL;
            const float* hp = hf32 + tid * HF32P;
            #pragma unroll 8
            for (int kk = 0; kk < 48; kk++){
                u64 hd = *(const u64*)&hp[2 * kk];
                ffma2(ax, hd, *(const u64*)&wex[2 * kk]);
                ffma2(ay, hd, *(const u64*)&wey[2 * kk]);
            }
            float2 o; o.x = red2(ax) + bex; o.y = red2(ay) + bey;
            *(float2*)(out + (b0 + tid) * 60 + 2 * t) = o;
        }
    }
}

extern "C" void kernel_launch(void* const* d_in, const int* in_sizes, int n_in,
                              void* d_out, int out_size)
{
    (void)n_in; (void)out_size;
    const float* traj  = (const float*)d_in[0];
    const float* cent  = (const float*)d_in[1];
    const float* Wih_c = (const float*)d_in[2];
    const float* Whh_c = (const float*)d_in[3];
    const float* bih_c = (const float*)d_in[4];
    const float* bhh_c = (const float*)d_in[5];
    const float* Wih_e = (const float*)d_in[6];
    const float* Whh_e = (const float*)d_in[7];
    const float* bih_e = (const float*)d_in[8];
    const float* bhh_e = (const float*)d_in[9];
    const float* Wih_d = (const float*)d_in[10];
    const float* Whh_d = (const float*)d_in[11];
    const float* bih_d = (const float*)d_in[12];
    const float* bhh_d = (const float*)d_in[13];
    const float* W_emb = (const float*)d_in[14];
    const float* b_emb = (const float*)d_in[15];
    float* out = (float*)d_out;

    const int B = in_sizes[0] / 40;   // input_traj [B][20][2]

    const int smc = (128 * 34 + 256 + 32 * 38) * 4;            //  23,296
    const int sme = (256 * 66 + 512 + 32 * 70) * 4;            //  78,592

    cudaFuncSetAttribute(lstm_rec<32, 100, 64, 4>, cudaFuncAttributeMaxDynamicSharedMemorySize, smc);
    cudaFuncSetAttribute(lstm_rec<64,  20,  0, 2>, cudaFuncAttributeMaxDynamicSharedMemorySize, sme);
    cudaFuncSetAttribute(lstm_dec_mma, cudaFuncAttributeMaxDynamicSharedMemorySize, SM_TOT);

    // centerline LSTM (H=32, T=100) -> g_h0/g_c0[.., 64..95]
    lstm_rec<32, 100, 64, 4><<<B / 32, 128, smc>>>(cent, Wih_c, Whh_c, bih_c, bhh_c);
    // encoder LSTM (H=64, T=20)    -> g_h0/g_c0[.., 0..63]
    lstm_rec<64,  20,  0, 2><<<B / 32, 256, sme>>>(traj, Wih_e, Whh_e, bih_e, bhh_e);
    // decoder on HMMA fp16 2-pass (H=96, 30 steps, 32 elems/CTA) -> out [B][30][2]
    lstm_dec_mma<<<B / 32, DNT, SM_TOT>>>(Wih_d, Whh_d, bih_d, bhh_d, W_emb, b_emb, out);
}